// round 3
// baseline (speedup 1.0000x reference)
#include <cuda_runtime.h>
#include <cuda_bf16.h>
#include <math_constants.h>
#include <mma.h>
#include <cstdint>

using namespace nvcuda;

// ---------------- output packing ----------------
#define LEN_RECON (512*4096)
#define LEN_DIST  (512*64*1024)
#define LEN_IDX   (512*64)
#define LEN_MU    (512*256)
#define LEN_LV    (512*256)
#define LEN_DMU   (512*768)
#define LEN_DLV   (512*768)

#define OFF_RECON 0
#define OFF_DIST  (OFF_RECON + LEN_RECON)
#define OFF_IDX   (OFF_DIST  + LEN_DIST)
#define OFF_MU    (OFF_IDX   + LEN_IDX)
#define OFF_LV    (OFF_MU    + LEN_MU)
#define OFF_DMU   (OFF_LV    + LEN_LV)
#define OFF_DLV   (OFF_DMU   + LEN_DMU)
#define OFF_PLV   (OFF_DLV   + LEN_DLV)

// ---------------- scratch ----------------
__device__ float g_feat[32768 * 512];
__device__ float g_hmax[512 * 512];
__device__ float g_h2[512 * 2048];
__device__ float g_h3[512 * 512];
__device__ float g_t[512 * 2048];
__device__ float g_p[512 * 1536];
__device__ float g_cat[512 * 2304];
__device__ float g_d[512 * 1536];
__device__ float g_z2[512 * 768];
__device__ float g_xr2[512 * 64];
__device__ float g_book2[64 * 1024];
__device__ unsigned long long g_keys[512 * 64];

// ================= wmma bf16x3 GEMM =================
// C[M,N] = act(A[M,K] @ W[N,K]^T + bias), fp32 in/out.
// fp32 split into bf16 hi+lo; 3 wmma per (hi*hi + hi*lo + lo*hi).
// Tile BM x BN, BK=32, warp tile 32x32, (BM/32)*(BN/32) warps.
template<int BM, int BN>
__global__ void k_mgemm(
    const float* __restrict__ A, int lda,
    const float* __restrict__ W, int K,
    const float* __restrict__ bias,
    float* __restrict__ C, int N, int act)
{
    constexpr int BK  = 32;
    constexpr int PAD = 40;                 // ldm mult of 8, stagger banks
    constexpr int WM  = BM / 32, WN = BN / 32, NW = WM * WN;

    extern __shared__ char smem[];
    __nv_bfloat16* Ahi = reinterpret_cast<__nv_bfloat16*>(smem);
    __nv_bfloat16* Alo = Ahi + BM * PAD;
    __nv_bfloat16* Bhi = Alo + BM * PAD;
    __nv_bfloat16* Blo = Bhi + BN * PAD;

    const int tid = threadIdx.x, wid = tid >> 5, lid = tid & 31;
    const int bm = blockIdx.y * BM, bn = blockIdx.x * BN;
    const int wm = wid % WM, wn = wid / WM;

    wmma::fragment<wmma::accumulator, 16, 16, 16, float> acc[2][2];
#pragma unroll
    for (int i = 0; i < 2; i++)
#pragma unroll
        for (int j = 0; j < 2; j++)
            wmma::fill_fragment(acc[i][j], 0.0f);

    for (int k0 = 0; k0 < K; k0 += BK) {
        // stage A (BM x 32) and B (BN x 32) as bf16 hi/lo
#pragma unroll 4
        for (int i = tid; i < BM * BK; i += NW * 32) {
            int m = i >> 5, k = i & 31;
            float f = A[(size_t)(bm + m) * lda + k0 + k];
            __nv_bfloat16 hi = __float2bfloat16(f);
            Ahi[m * PAD + k] = hi;
            Alo[m * PAD + k] = __float2bfloat16(f - __bfloat162float(hi));
        }
#pragma unroll 4
        for (int i = tid; i < BN * BK; i += NW * 32) {
            int n = i >> 5, k = i & 31;
            float f = W[(size_t)(bn + n) * K + k0 + k];
            __nv_bfloat16 hi = __float2bfloat16(f);
            Bhi[n * PAD + k] = hi;
            Blo[n * PAD + k] = __float2bfloat16(f - __bfloat162float(hi));
        }
        __syncthreads();

#pragma unroll
        for (int kk = 0; kk < BK; kk += 16) {
            wmma::fragment<wmma::matrix_a, 16, 16, 16, __nv_bfloat16, wmma::row_major> ah[2], al[2];
            wmma::fragment<wmma::matrix_b, 16, 16, 16, __nv_bfloat16, wmma::col_major> bh[2], bl[2];
#pragma unroll
            for (int i = 0; i < 2; i++) {
                const __nv_bfloat16* pa = Ahi + (wm * 32 + i * 16) * PAD + kk;
                wmma::load_matrix_sync(ah[i], pa, PAD);
                wmma::load_matrix_sync(al[i], pa + (Alo - Ahi), PAD);
            }
#pragma unroll
            for (int j = 0; j < 2; j++) {
                const __nv_bfloat16* pb = Bhi + (wn * 32 + j * 16) * PAD + kk;
                wmma::load_matrix_sync(bh[j], pb, PAD);
                wmma::load_matrix_sync(bl[j], pb + (Blo - Bhi), PAD);
            }
#pragma unroll
            for (int i = 0; i < 2; i++)
#pragma unroll
                for (int j = 0; j < 2; j++) {
                    wmma::mma_sync(acc[i][j], ah[i], bh[j], acc[i][j]);
                    wmma::mma_sync(acc[i][j], ah[i], bl[j], acc[i][j]);
                    wmma::mma_sync(acc[i][j], al[i], bh[j], acc[i][j]);
                }
        }
        __syncthreads();
    }

    // epilogue: per-warp 32x32 patch in smem -> bias + act -> coalesced stores
    float* patch = reinterpret_cast<float*>(smem) + wid * 1024;
#pragma unroll
    for (int i = 0; i < 2; i++)
#pragma unroll
        for (int j = 0; j < 2; j++)
            wmma::store_matrix_sync(patch + i * 16 * 32 + j * 16, acc[i][j], 32,
                                    wmma::mem_row_major);
    __syncwarp();

    const int cbase = bn + wn * 32;
#pragma unroll
    for (int it = 0; it < 8; it++) {
        int r  = it * 4 + (lid >> 3);
        int c0 = (lid & 7) * 4;
        float4 v;
        float* vp = reinterpret_cast<float*>(&v);
#pragma unroll
        for (int j = 0; j < 4; j++) {
            float rr = patch[r * 32 + c0 + j] + __ldg(&bias[cbase + c0 + j]);
            if (act) rr = rr > 0.f ? rr : 0.2f * rr;
            vp[j] = rr;
        }
        *reinterpret_cast<float4*>(&C[(size_t)(bm + wm * 32 + r) * N + cbase + c0]) = v;
    }
}

// ================= elementwise helpers =================
__global__ void k_maxpool(const float* __restrict__ feat, float* __restrict__ hmax)
{
    int idx = blockIdx.x * blockDim.x + threadIdx.x;
    int b = idx >> 9, h = idx & 511;
    float m = -CUDART_INF_F;
#pragma unroll 8
    for (int c = 0; c < 64; c++)
        m = fmaxf(m, feat[(((size_t)b * 64 + c) << 9) + h]);
    hmax[idx] = m;
}

__global__ void k_copyslice(const float* __restrict__ src, int ld, int col0, int ncols,
                            float* __restrict__ dst, int total)
{
    int idx = blockIdx.x * blockDim.x + threadIdx.x;
    if (idx >= total) return;
    int b = idx / ncols, j = idx - b * ncols;
    dst[idx] = src[(size_t)b * ld + col0 + j];
}

__global__ void k_cat(const float* __restrict__ z1, const float* __restrict__ h,
                      float* __restrict__ dst)
{
    int idx = blockIdx.x * blockDim.x + threadIdx.x;
    if (idx >= 512 * 2304) return;
    int b = idx / 2304, j = idx - b * 2304;
    dst[idx] = (j < 256) ? z1[(size_t)b * 512 + j] : h[(size_t)b * 2048 + (j - 256)];
}

__global__ void k_z2(const float* __restrict__ d, const float* __restrict__ p,
                     float* __restrict__ z2)
{
    int idx = blockIdx.x * blockDim.x + threadIdx.x;
    if (idx >= 512 * 768) return;
    int b = idx / 768, j = idx - b * 768;
    z2[idx] = d[(size_t)b * 1536 + j] + p[(size_t)b * 1536 + j];
}

__global__ void k_initkeys(unsigned long long* __restrict__ keys)
{
    int idx = blockIdx.x * blockDim.x + threadIdx.x;
    if (idx < 512 * 64) keys[idx] = ~0ull;
}

__global__ void k_rowsq(const float* __restrict__ src, float* __restrict__ dst, int nrows)
{
    int idx = blockIdx.x * blockDim.x + threadIdx.x;
    if (idx >= nrows) return;
    const float4* p = reinterpret_cast<const float4*>(src + (size_t)idx * 64);
    float s = 0.f;
#pragma unroll
    for (int i = 0; i < 16; i++) {
        float4 v = p[i];
        s += v.x * v.x + v.y * v.y + v.z * v.z + v.w * v.w;
    }
    dst[idx] = s;
}

// ================= dist + fused argmin (SIMT fp32) =================
__device__ __forceinline__ unsigned int f32_ordered(float f)
{
    unsigned int b = __float_as_uint(f);
    return (b & 0x80000000u) ? ~b : (b | 0x80000000u);
}

__global__ __launch_bounds__(256) void k_dist(
    const float* __restrict__ recon,
    const float* __restrict__ book,
    const float* __restrict__ xr2,
    const float* __restrict__ book2,
    float* __restrict__ dist,
    unsigned long long* __restrict__ keys)
{
    __shared__ float As[64][65];
    __shared__ float Ws[64][65];
    const int tid = threadIdx.x;
    const int tx = tid & 15, ty = tid >> 4;
    const int c  = blockIdx.z;
    const int bm = blockIdx.y * 64;
    const int sn = blockIdx.x * 64;

#pragma unroll
    for (int i = 0; i < 16; i++) {
        int idx = tid + i * 256;
        int m = idx >> 6, e = idx & 63;
        As[e][m] = recon[(size_t)(bm + m) * 4096 + c * 64 + e];
        Ws[e][m] = book[((size_t)c * 1024 + sn + m) * 64 + e];
    }
    __syncthreads();

    float acc[4][4] = {};
#pragma unroll 16
    for (int e = 0; e < 64; e++) {
        float a[4], w[4];
#pragma unroll
        for (int i = 0; i < 4; i++) a[i] = As[e][ty * 4 + i];
#pragma unroll
        for (int j = 0; j < 4; j++) w[j] = Ws[e][tx * 4 + j];
#pragma unroll
        for (int i = 0; i < 4; i++)
#pragma unroll
            for (int j = 0; j < 4; j++)
                acc[i][j] = fmaf(a[i], w[j], acc[i][j]);
    }

#pragma unroll
    for (int i = 0; i < 4; i++) {
        int b = bm + ty * 4 + i;
        float x2 = xr2[b * 64 + c];
        float4 v;
        float* vp = reinterpret_cast<float*>(&v);
        unsigned long long kbest = ~0ull;
#pragma unroll
        for (int j = 0; j < 4; j++) {
            int s = sn + tx * 4 + j;
            float dval = x2 + __ldg(&book2[c * 1024 + s]) - 2.f * acc[i][j];
            vp[j] = dval;
            unsigned long long key = ((unsigned long long)f32_ordered(dval) << 32) |
                                     (unsigned int)s;
            kbest = min(kbest, key);
        }
        *reinterpret_cast<float4*>(&dist[((size_t)b * 64 + c) * 1024 + sn + tx * 4]) = v;
#pragma unroll
        for (int off = 8; off; off >>= 1) {
            unsigned long long o = __shfl_xor_sync(0xffffffffu, kbest, off, 16);
            kbest = min(kbest, o);
        }
        if (tx == 0) atomicMin(&keys[b * 64 + c], kbest);
    }
}

__global__ void k_writeidx(const unsigned long long* __restrict__ keys,
                           float* __restrict__ out)
{
    int idx = blockIdx.x * blockDim.x + threadIdx.x;
    if (idx < 512 * 64)
        out[idx] = (float)(unsigned int)(keys[idx] & 0xFFFFFFFFull);
}

// ================= launcher =================
extern "C" void kernel_launch(void* const* d_in, const int* in_sizes, int n_in,
                              void* d_out, int out_size)
{
    const float* x        = (const float*)d_in[0];
    const float* codebook = (const float*)d_in[1];
    const float* enc_w1   = (const float*)d_in[2];
    const float* enc_b1   = (const float*)d_in[3];
    const float* enc_w2   = (const float*)d_in[4];
    const float* enc_b2   = (const float*)d_in[5];
    const float* inf1_w   = (const float*)d_in[6];
    const float* inf1_b   = (const float*)d_in[7];
    const float* inf2_w1  = (const float*)d_in[8];
    const float* inf2_b1  = (const float*)d_in[9];
    const float* inf2_w2  = (const float*)d_in[10];
    const float* inf2_b2  = (const float*)d_in[11];
    const float* prior_w1 = (const float*)d_in[12];
    const float* prior_b1 = (const float*)d_in[13];
    const float* prior_w2 = (const float*)d_in[14];
    const float* prior_b2 = (const float*)d_in[15];
    const float* dec_w1   = (const float*)d_in[16];
    const float* dec_b1   = (const float*)d_in[17];
    const float* dec_w2   = (const float*)d_in[18];
    const float* dec_b2   = (const float*)d_in[19];
    float* out = (float*)d_out;

    float *feat, *hmax, *h2, *h3, *t, *p, *cat, *d, *z2, *xr2, *book2;
    unsigned long long* keys;
    cudaGetSymbolAddress((void**)&feat,  g_feat);
    cudaGetSymbolAddress((void**)&hmax,  g_hmax);
    cudaGetSymbolAddress((void**)&h2,    g_h2);
    cudaGetSymbolAddress((void**)&h3,    g_h3);
    cudaGetSymbolAddress((void**)&t,     g_t);
    cudaGetSymbolAddress((void**)&p,     g_p);
    cudaGetSymbolAddress((void**)&cat,   g_cat);
    cudaGetSymbolAddress((void**)&d,     g_d);
    cudaGetSymbolAddress((void**)&z2,    g_z2);
    cudaGetSymbolAddress((void**)&xr2,   g_xr2);
    cudaGetSymbolAddress((void**)&book2, g_book2);
    cudaGetSymbolAddress((void**)&keys,  g_keys);

    // (128,128) smem: max(stage 40960, epi 65536) = 65536 -> needs opt-in
    cudaFuncSetAttribute(k_mgemm<128,128>, cudaFuncAttributeMaxDynamicSharedMemorySize, 65536);
    // (64,64) smem: max(stage 20480, epi 16384) = 20480 (under default, set anyway)
    cudaFuncSetAttribute(k_mgemm<64,64>,   cudaFuncAttributeMaxDynamicSharedMemorySize, 20480);

    // 1) enc1: feat = lrelu(x(32768,64) @ enc_w1^T + b1) -> (32768, 512)
    k_mgemm<128,128><<<dim3(512/128, 32768/128), 512, 65536>>>(x, 64, enc_w1, 64, enc_b1, feat, 512, 1);
    // 2) max-pool over codes
    k_maxpool<<<(512*512)/256, 256>>>(feat, hmax);
    // 3) enc2: h2 = hmax @ enc_w2^T + b2 -> (512, 2048)
    k_mgemm<64,64><<<dim3(2048/64, 512/64), 128, 20480>>>(hmax, 512, enc_w2, 512, enc_b2, h2, 2048, 0);
    // 4) inf1: h3 = h2 @ inf1_w^T + b -> (512, 512)
    k_mgemm<64,64><<<dim3(512/64, 512/64), 128, 20480>>>(h2, 2048, inf1_w, 2048, inf1_b, h3, 512, 0);
    k_copyslice<<<(512*256+255)/256, 256>>>(h3, 512, 0,   256, out + OFF_MU, 512*256);
    k_copyslice<<<(512*256+255)/256, 256>>>(h3, 512, 256, 256, out + OFF_LV, 512*256);
    // 5) prior
    k_mgemm<64,64><<<dim3(2048/64, 512/64), 128, 20480>>>(h3, 512, prior_w1, 256, prior_b1, t, 2048, 1);
    k_mgemm<64,64><<<dim3(1536/64, 512/64), 128, 20480>>>(t, 2048, prior_w2, 2048, prior_b2, p, 1536, 0);
    k_copyslice<<<(512*768+255)/256, 256>>>(p, 1536, 768, 768, out + OFF_PLV, 512*768);
    // 6) inf2
    k_cat<<<(512*2304+255)/256, 256>>>(h3, h2, cat);
    k_mgemm<64,64><<<dim3(2048/64, 512/64), 128, 20480>>>(cat, 2304, inf2_w1, 2304, inf2_b1, t, 2048, 1);
    k_mgemm<64,64><<<dim3(1536/64, 512/64), 128, 20480>>>(t, 2048, inf2_w2, 2048, inf2_b2, d, 1536, 0);
    k_copyslice<<<(512*768+255)/256, 256>>>(d, 1536, 0,   768, out + OFF_DMU, 512*768);
    k_copyslice<<<(512*768+255)/256, 256>>>(d, 1536, 768, 768, out + OFF_DLV, 512*768);
    // 7) z2 = d_mu + p_mu
    k_z2<<<(512*768+255)/256, 256>>>(d, p, z2);
    // 8) decoder
    k_mgemm<64,64><<<dim3(2048/64, 512/64), 128, 20480>>>(z2, 768, dec_w1, 768, dec_b1, t, 2048, 1);
    k_mgemm<64,64><<<dim3(4096/64, 512/64), 128, 20480>>>(t, 2048, dec_w2, 2048, dec_b2, out + OFF_RECON, 4096, 0);
    // 9) dist + argmin
    k_rowsq<<<(512*64+255)/256, 256>>>(out + OFF_RECON, xr2, 512*64);
    k_rowsq<<<(64*1024+255)/256, 256>>>(codebook, book2, 64*1024);
    k_initkeys<<<(512*64+255)/256, 256>>>(keys);
    k_dist<<<dim3(1024/64, 512/64, 64), 256>>>(out + OFF_RECON, codebook, xr2, book2,
                                               out + OFF_DIST, keys);
    k_writeidx<<<(512*64+255)/256, 256>>>(keys, out + OFF_IDX);
}

// round 4
// speedup vs baseline: 2.8576x; 2.8576x over previous
#include <cuda_runtime.h>
#include <cuda_bf16.h>
#include <math_constants.h>
#include <mma.h>
#include <cstdint>

using namespace nvcuda;

// ---------------- output packing ----------------
#define LEN_RECON (512*4096)
#define LEN_DIST  (512*64*1024)
#define LEN_IDX   (512*64)
#define LEN_MU    (512*256)
#define LEN_LV    (512*256)
#define LEN_DMU   (512*768)
#define LEN_DLV   (512*768)

#define OFF_RECON 0
#define OFF_DIST  (OFF_RECON + LEN_RECON)
#define OFF_IDX   (OFF_DIST  + LEN_DIST)
#define OFF_MU    (OFF_IDX   + LEN_IDX)
#define OFF_LV    (OFF_MU    + LEN_MU)
#define OFF_DMU   (OFF_LV    + LEN_LV)
#define OFF_DLV   (OFF_DMU   + LEN_DMU)
#define OFF_PLV   (OFF_DLV   + LEN_DLV)

// ---------------- scratch ----------------
__device__ unsigned int g_hmaxu[512 * 512];
__device__ float g_hmax[512 * 512];
__device__ float g_h2[512 * 2048];
__device__ float g_h3[512 * 512];
__device__ float g_t[512 * 2048];
__device__ float g_p[512 * 1536];
__device__ float g_cat[512 * 2304];
__device__ float g_d[512 * 1536];
__device__ float g_z2[512 * 768];
__device__ float g_xr2[512 * 64];
__device__ float g_book2[64 * 1024];
__device__ unsigned long long g_keys[512 * 64];

__device__ __forceinline__ unsigned int f32_ordered(float f)
{
    unsigned int b = __float_as_uint(f);
    return (b & 0x80000000u) ? ~b : (b | 0x80000000u);
}
__device__ __forceinline__ float f32_unordered(unsigned int u)
{
    return __uint_as_float((u & 0x80000000u) ? (u & 0x7FFFFFFFu) : ~u);
}

// ================= pipelined wmma bf16x3 GEMM =================
// C[M,N] = act(A[M,K] @ W[N,K]^T + bias). BM=128, BN=64, BK=32, 256 thr, 8 warps.
// mode 0: store C.  mode 1: no C store; atomicMax ordered-uint maxpool over
//         row groups of 64 (m = b*64 + c) into hmaxu[b*512 + n].
__global__ __launch_bounds__(256) void k_wgemm(
    const float* __restrict__ A, int lda,
    const float* __restrict__ W, int K,
    const float* __restrict__ bias,
    float* __restrict__ C, int N, int act, int mode,
    unsigned int* __restrict__ hmaxu)
{
    constexpr int BM = 128, BN = 64, BK = 32, PAD = 40;
    extern __shared__ char smem[];
    __nv_bfloat16* Ahi = reinterpret_cast<__nv_bfloat16*>(smem);
    __nv_bfloat16* Alo = Ahi + BM * PAD;
    __nv_bfloat16* Bhi = Alo + BM * PAD;
    __nv_bfloat16* Blo = Bhi + BN * PAD;

    const int tid = threadIdx.x, wid = tid >> 5, lid = tid & 31;
    const int bm = blockIdx.y * BM, bn = blockIdx.x * BN;
    const int wm = wid & 3, wn = wid >> 2;    // 4 x 2 warps -> 32x32 each

    // per-thread staging registers: A 4 x float4, B 2 x float4
    float4 ar[4], br[2];
    const int arow = tid >> 3, ak4 = tid & 7;         // A: rows 0..127 via +32/iter
    // (each i adds 256 threads -> +32 rows)

    wmma::fragment<wmma::accumulator, 16, 16, 16, float> acc[2][2];
#pragma unroll
    for (int i = 0; i < 2; i++)
#pragma unroll
        for (int j = 0; j < 2; j++)
            wmma::fill_fragment(acc[i][j], 0.0f);

    const int nt = K / BK;

#define LOAD_REGS(k0)                                                          \
    {                                                                          \
        _Pragma("unroll")                                                      \
        for (int i = 0; i < 4; i++)                                            \
            ar[i] = *reinterpret_cast<const float4*>(                          \
                &A[(size_t)(bm + arow + i * 32) * lda + (k0) + ak4 * 4]);      \
        _Pragma("unroll")                                                      \
        for (int i = 0; i < 2; i++)                                            \
            br[i] = *reinterpret_cast<const float4*>(                          \
                &W[(size_t)(bn + arow + i * 32) * K + (k0) + ak4 * 4]);        \
    }

#define STAGE()                                                                \
    {                                                                          \
        _Pragma("unroll")                                                      \
        for (int i = 0; i < 4; i++) {                                          \
            int r = arow + i * 32;                                             \
            float4 v = ar[i];                                                  \
            __nv_bfloat16 hx = __float2bfloat16(v.x);                          \
            __nv_bfloat16 hy = __float2bfloat16(v.y);                          \
            __nv_bfloat16 hz = __float2bfloat16(v.z);                          \
            __nv_bfloat16 hw = __float2bfloat16(v.w);                          \
            __nv_bfloat16* pa = Ahi + r * PAD + ak4 * 4;                       \
            *reinterpret_cast<__nv_bfloat162*>(pa)     = __halves2bfloat162(hx, hy); \
            *reinterpret_cast<__nv_bfloat162*>(pa + 2) = __halves2bfloat162(hz, hw); \
            __nv_bfloat16* pl = Alo + r * PAD + ak4 * 4;                       \
            *reinterpret_cast<__nv_bfloat162*>(pl) = __halves2bfloat162(       \
                __float2bfloat16(v.x - __bfloat162float(hx)),                  \
                __float2bfloat16(v.y - __bfloat162float(hy)));                 \
            *reinterpret_cast<__nv_bfloat162*>(pl + 2) = __halves2bfloat162(   \
                __float2bfloat16(v.z - __bfloat162float(hz)),                  \
                __float2bfloat16(v.w - __bfloat162float(hw)));                 \
        }                                                                      \
        _Pragma("unroll")                                                      \
        for (int i = 0; i < 2; i++) {                                          \
            int r = arow + i * 32;                                             \
            float4 v = br[i];                                                  \
            __nv_bfloat16 hx = __float2bfloat16(v.x);                          \
            __nv_bfloat16 hy = __float2bfloat16(v.y);                          \
            __nv_bfloat16 hz = __float2bfloat16(v.z);                          \
            __nv_bfloat16 hw = __float2bfloat16(v.w);                          \
            __nv_bfloat16* pb = Bhi + r * PAD + ak4 * 4;                       \
            *reinterpret_cast<__nv_bfloat162*>(pb)     = __halves2bfloat162(hx, hy); \
            *reinterpret_cast<__nv_bfloat162*>(pb + 2) = __halves2bfloat162(hz, hw); \
            __nv_bfloat16* pl = Blo + r * PAD + ak4 * 4;                       \
            *reinterpret_cast<__nv_bfloat162*>(pl) = __halves2bfloat162(       \
                __float2bfloat16(v.x - __bfloat162float(hx)),                  \
                __float2bfloat16(v.y - __bfloat162float(hy)));                 \
            *reinterpret_cast<__nv_bfloat162*>(pl + 2) = __halves2bfloat162(   \
                __float2bfloat16(v.z - __bfloat162float(hz)),                  \
                __float2bfloat16(v.w - __bfloat162float(hw)));                 \
        }                                                                      \
    }

    LOAD_REGS(0);
    STAGE();
    __syncthreads();

    for (int t = 0; t < nt; t++) {
        if (t + 1 < nt) LOAD_REGS((t + 1) * BK);

#pragma unroll
        for (int kk = 0; kk < BK; kk += 16) {
            wmma::fragment<wmma::matrix_a, 16, 16, 16, __nv_bfloat16, wmma::row_major> ah[2], al[2];
            wmma::fragment<wmma::matrix_b, 16, 16, 16, __nv_bfloat16, wmma::col_major> bh[2], bl[2];
#pragma unroll
            for (int i = 0; i < 2; i++) {
                const __nv_bfloat16* pa = Ahi + (wm * 32 + i * 16) * PAD + kk;
                wmma::load_matrix_sync(ah[i], pa, PAD);
                wmma::load_matrix_sync(al[i], pa + BM * PAD, PAD);
            }
#pragma unroll
            for (int j = 0; j < 2; j++) {
                const __nv_bfloat16* pb = Bhi + (wn * 32 + j * 16) * PAD + kk;
                wmma::load_matrix_sync(bh[j], pb, PAD);
                wmma::load_matrix_sync(bl[j], pb + BN * PAD, PAD);
            }
#pragma unroll
            for (int i = 0; i < 2; i++)
#pragma unroll
                for (int j = 0; j < 2; j++) {
                    wmma::mma_sync(acc[i][j], ah[i], bh[j], acc[i][j]);
                    wmma::mma_sync(acc[i][j], ah[i], bl[j], acc[i][j]);
                    wmma::mma_sync(acc[i][j], al[i], bh[j], acc[i][j]);
                }
        }
        __syncthreads();
        if (t + 1 < nt) { STAGE(); __syncthreads(); }
    }

    // epilogue: per-warp 32x32 patch
    float* patch = reinterpret_cast<float*>(smem) + wid * 1024;
#pragma unroll
    for (int i = 0; i < 2; i++)
#pragma unroll
        for (int j = 0; j < 2; j++)
            wmma::store_matrix_sync(patch + i * 16 * 32 + j * 16, acc[i][j], 32,
                                    wmma::mem_row_major);
    __syncwarp();

    const int cbase = bn + wn * 32;
    const int c0 = (lid & 7) * 4;
    if (mode == 0) {
#pragma unroll
        for (int it = 0; it < 8; it++) {
            int r = it * 4 + (lid >> 3);
            float4 v;
            float* vp = reinterpret_cast<float*>(&v);
#pragma unroll
            for (int j = 0; j < 4; j++) {
                float rr = patch[r * 32 + c0 + j] + __ldg(&bias[cbase + c0 + j]);
                if (act) rr = rr > 0.f ? rr : 0.2f * rr;
                vp[j] = rr;
            }
            *reinterpret_cast<float4*>(&C[(size_t)(bm + wm * 32 + r) * N + cbase + c0]) = v;
        }
    } else {
        float mx[4] = {-CUDART_INF_F, -CUDART_INF_F, -CUDART_INF_F, -CUDART_INF_F};
#pragma unroll
        for (int it = 0; it < 8; it++) {
            int r = it * 4 + (lid >> 3);
#pragma unroll
            for (int j = 0; j < 4; j++) {
                float rr = patch[r * 32 + c0 + j] + __ldg(&bias[cbase + c0 + j]);
                rr = rr > 0.f ? rr : 0.2f * rr;   // enc1 always lrelu
                mx[j] = fmaxf(mx[j], rr);
            }
        }
        int b = (bm + wm * 32) >> 6;
#pragma unroll
        for (int j = 0; j < 4; j++)
            atomicMax(&hmaxu[b * 512 + cbase + c0 + j], f32_ordered(mx[j]));
    }
}

// ================= elementwise helpers =================
__global__ void k_inithmax(unsigned int* __restrict__ hmaxu)
{
    int idx = blockIdx.x * blockDim.x + threadIdx.x;
    if (idx < 512 * 512) hmaxu[idx] = f32_ordered(-CUDART_INF_F);
}

__global__ void k_cvthmax(const unsigned int* __restrict__ hmaxu, float* __restrict__ hmax)
{
    int idx = blockIdx.x * blockDim.x + threadIdx.x;
    if (idx < 512 * 512) hmax[idx] = f32_unordered(hmaxu[idx]);
}

__global__ void k_copyslice(const float* __restrict__ src, int ld, int col0, int ncols,
                            float* __restrict__ dst, int total)
{
    int idx = blockIdx.x * blockDim.x + threadIdx.x;
    if (idx >= total) return;
    int b = idx / ncols, j = idx - b * ncols;
    dst[idx] = src[(size_t)b * ld + col0 + j];
}

__global__ void k_cat(const float* __restrict__ z1, const float* __restrict__ h,
                      float* __restrict__ dst)
{
    int idx = blockIdx.x * blockDim.x + threadIdx.x;
    if (idx >= 512 * 2304) return;
    int b = idx / 2304, j = idx - b * 2304;
    dst[idx] = (j < 256) ? z1[(size_t)b * 512 + j] : h[(size_t)b * 2048 + (j - 256)];
}

__global__ void k_z2(const float* __restrict__ d, const float* __restrict__ p,
                     float* __restrict__ z2)
{
    int idx = blockIdx.x * blockDim.x + threadIdx.x;
    if (idx >= 512 * 768) return;
    int b = idx / 768, j = idx - b * 768;
    z2[idx] = d[(size_t)b * 1536 + j] + p[(size_t)b * 1536 + j];
}

__global__ void k_initkeys(unsigned long long* __restrict__ keys)
{
    int idx = blockIdx.x * blockDim.x + threadIdx.x;
    if (idx < 512 * 64) keys[idx] = ~0ull;
}

__global__ void k_rowsq(const float* __restrict__ src, float* __restrict__ dst, int nrows)
{
    int idx = blockIdx.x * blockDim.x + threadIdx.x;
    if (idx >= nrows) return;
    const float4* p = reinterpret_cast<const float4*>(src + (size_t)idx * 64);
    float s = 0.f;
#pragma unroll
    for (int i = 0; i < 16; i++) {
        float4 v = p[i];
        s += v.x * v.x + v.y * v.y + v.z * v.z + v.w * v.w;
    }
    dst[idx] = s;
}

// ================= dist + fused argmin (SIMT fp32) =================
__global__ __launch_bounds__(256) void k_dist(
    const float* __restrict__ recon,
    const float* __restrict__ book,
    const float* __restrict__ xr2,
    const float* __restrict__ book2,
    float* __restrict__ dist,
    unsigned long long* __restrict__ keys)
{
    __shared__ float As[64][68];
    __shared__ float Ws[64][68];
    const int tid = threadIdx.x;
    const int tx = tid & 15, ty = tid >> 4;
    const int c  = blockIdx.z;
    const int bm = blockIdx.y * 64;
    const int sn = blockIdx.x * 64;

#pragma unroll
    for (int i = 0; i < 16; i++) {
        int idx = tid + i * 256;
        int m = idx >> 6, e = idx & 63;
        As[e][m] = recon[(size_t)(bm + m) * 4096 + c * 64 + e];
        Ws[e][m] = book[((size_t)c * 1024 + sn + m) * 64 + e];
    }
    __syncthreads();

    float acc[4][4] = {};
#pragma unroll 16
    for (int e = 0; e < 64; e++) {
        float a[4], w[4];
#pragma unroll
        for (int i = 0; i < 4; i++) a[i] = As[e][ty * 4 + i];
#pragma unroll
        for (int j = 0; j < 4; j++) w[j] = Ws[e][tx * 4 + j];
#pragma unroll
        for (int i = 0; i < 4; i++)
#pragma unroll
            for (int j = 0; j < 4; j++)
                acc[i][j] = fmaf(a[i], w[j], acc[i][j]);
    }

#pragma unroll
    for (int i = 0; i < 4; i++) {
        int b = bm + ty * 4 + i;
        float x2 = xr2[b * 64 + c];
        float4 v;
        float* vp = reinterpret_cast<float*>(&v);
        unsigned long long kbest = ~0ull;
#pragma unroll
        for (int j = 0; j < 4; j++) {
            int s = sn + tx * 4 + j;
            float dval = x2 + __ldg(&book2[c * 1024 + s]) - 2.f * acc[i][j];
            vp[j] = dval;
            unsigned long long key = ((unsigned long long)f32_ordered(dval) << 32) |
                                     (unsigned int)s;
            kbest = min(kbest, key);
        }
        *reinterpret_cast<float4*>(&dist[((size_t)b * 64 + c) * 1024 + sn + tx * 4]) = v;
#pragma unroll
        for (int off = 8; off; off >>= 1) {
            unsigned long long o = __shfl_xor_sync(0xffffffffu, kbest, off, 16);
            kbest = min(kbest, o);
        }
        if (tx == 0) atomicMin(&keys[b * 64 + c], kbest);
    }
}

__global__ void k_writeidx(const unsigned long long* __restrict__ keys,
                           float* __restrict__ out)
{
    int idx = blockIdx.x * blockDim.x + threadIdx.x;
    if (idx < 512 * 64)
        out[idx] = (float)(unsigned int)(keys[idx] & 0xFFFFFFFFull);
}

// ================= launcher =================
#define GEMM_SMEM 32768

extern "C" void kernel_launch(void* const* d_in, const int* in_sizes, int n_in,
                              void* d_out, int out_size)
{
    const float* x        = (const float*)d_in[0];
    const float* codebook = (const float*)d_in[1];
    const float* enc_w1   = (const float*)d_in[2];
    const float* enc_b1   = (const float*)d_in[3];
    const float* enc_w2   = (const float*)d_in[4];
    const float* enc_b2   = (const float*)d_in[5];
    const float* inf1_w   = (const float*)d_in[6];
    const float* inf1_b   = (const float*)d_in[7];
    const float* inf2_w1  = (const float*)d_in[8];
    const float* inf2_b1  = (const float*)d_in[9];
    const float* inf2_w2  = (const float*)d_in[10];
    const float* inf2_b2  = (const float*)d_in[11];
    const float* prior_w1 = (const float*)d_in[12];
    const float* prior_b1 = (const float*)d_in[13];
    const float* prior_w2 = (const float*)d_in[14];
    const float* prior_b2 = (const float*)d_in[15];
    const float* dec_w1   = (const float*)d_in[16];
    const float* dec_b1   = (const float*)d_in[17];
    const float* dec_w2   = (const float*)d_in[18];
    const float* dec_b2   = (const float*)d_in[19];
    float* out = (float*)d_out;

    float *hmax, *h2, *h3, *t, *p, *cat, *d, *z2, *xr2, *book2;
    unsigned int* hmaxu;
    unsigned long long* keys;
    cudaGetSymbolAddress((void**)&hmaxu, g_hmaxu);
    cudaGetSymbolAddress((void**)&hmax,  g_hmax);
    cudaGetSymbolAddress((void**)&h2,    g_h2);
    cudaGetSymbolAddress((void**)&h3,    g_h3);
    cudaGetSymbolAddress((void**)&t,     g_t);
    cudaGetSymbolAddress((void**)&p,     g_p);
    cudaGetSymbolAddress((void**)&cat,   g_cat);
    cudaGetSymbolAddress((void**)&d,     g_d);
    cudaGetSymbolAddress((void**)&z2,    g_z2);
    cudaGetSymbolAddress((void**)&xr2,   g_xr2);
    cudaGetSymbolAddress((void**)&book2, g_book2);
    cudaGetSymbolAddress((void**)&keys,  g_keys);

    cudaFuncSetAttribute(k_wgemm, cudaFuncAttributeMaxDynamicSharedMemorySize, GEMM_SMEM);

    // 1) enc1 fused with maxpool: lrelu(x(32768,64) @ enc_w1^T + b1) -> max over c
    k_inithmax<<<(512*512+255)/256, 256>>>(hmaxu);
    k_wgemm<<<dim3(512/64, 32768/128), 256, GEMM_SMEM>>>(x, 64, enc_w1, 64, enc_b1,
                                                         nullptr, 512, 1, 1, hmaxu);
    k_cvthmax<<<(512*512+255)/256, 256>>>(hmaxu, hmax);
    // 3) enc2: h2 = hmax @ enc_w2^T + b2 -> (512, 2048)
    k_wgemm<<<dim3(2048/64, 512/128), 256, GEMM_SMEM>>>(hmax, 512, enc_w2, 512, enc_b2,
                                                        h2, 2048, 0, 0, nullptr);
    // 4) inf1: h3 = h2 @ inf1_w^T + b -> (512, 512)
    k_wgemm<<<dim3(512/64, 512/128), 256, GEMM_SMEM>>>(h2, 2048, inf1_w, 2048, inf1_b,
                                                       h3, 512, 0, 0, nullptr);
    k_copyslice<<<(512*256+255)/256, 256>>>(h3, 512, 0,   256, out + OFF_MU, 512*256);
    k_copyslice<<<(512*256+255)/256, 256>>>(h3, 512, 256, 256, out + OFF_LV, 512*256);
    // 5) prior
    k_wgemm<<<dim3(2048/64, 512/128), 256, GEMM_SMEM>>>(h3, 512, prior_w1, 256, prior_b1,
                                                        t, 2048, 1, 0, nullptr);
    k_wgemm<<<dim3(1536/64, 512/128), 256, GEMM_SMEM>>>(t, 2048, prior_w2, 2048, prior_b2,
                                                        p, 1536, 0, 0, nullptr);
    k_copyslice<<<(512*768+255)/256, 256>>>(p, 1536, 768, 768, out + OFF_PLV, 512*768);
    // 6) inf2
    k_cat<<<(512*2304+255)/256, 256>>>(h3, h2, cat);
    k_wgemm<<<dim3(2048/64, 512/128), 256, GEMM_SMEM>>>(cat, 2304, inf2_w1, 2304, inf2_b1,
                                                        t, 2048, 1, 0, nullptr);
    k_wgemm<<<dim3(1536/64, 512/128), 256, GEMM_SMEM>>>(t, 2048, inf2_w2, 2048, inf2_b2,
                                                        d, 1536, 0, 0, nullptr);
    k_copyslice<<<(512*768+255)/256, 256>>>(d, 1536, 0,   768, out + OFF_DMU, 512*768);
    k_copyslice<<<(512*768+255)/256, 256>>>(d, 1536, 768, 768, out + OFF_DLV, 512*768);
    // 7) z2 = d_mu + p_mu
    k_z2<<<(512*768+255)/256, 256>>>(d, p, z2);
    // 8) decoder
    k_wgemm<<<dim3(2048/64, 512/128), 256, GEMM_SMEM>>>(z2, 768, dec_w1, 768, dec_b1,
                                                        t, 2048, 1, 0, nullptr);
    k_wgemm<<<dim3(4096/64, 512/128), 256, GEMM_SMEM>>>(t, 2048, dec_w2, 2048, dec_b2,
                                                        out + OFF_RECON, 4096, 0, 0, nullptr);
    // 9) dist + argmin
    k_rowsq<<<(512*64+255)/256, 256>>>(out + OFF_RECON, xr2, 512*64);
    k_rowsq<<<(64*1024+255)/256, 256>>>(codebook, book2, 64*1024);
    k_initkeys<<<(512*64+255)/256, 256>>>(keys);
    k_dist<<<dim3(1024/64, 512/64, 64), 256>>>(out + OFF_RECON, codebook, xr2, book2,
                                               out + OFF_DIST, keys);
    k_writeidx<<<(512*64+255)/256, 256>>>(keys, out + OFF_IDX);
}